// round 14
// baseline (speedup 1.0000x reference)
#include <cuda_runtime.h>
#include <cuda_bf16.h>
#include <math.h>
#include <stdint.h>

#define NN 40000
#define NE 640000
#define FIN 64
#define FE 16
#define NG 1000
#define HD 256
#define OD 128

#define SCB 256
#define NSCB ((NN + SCB - 1) / SCB)   // 157

#define SMEMSZ 55296

// ---------------- scratch (device globals) ----------------
__device__ __align__(16) int   d_src[NE];
__device__ __align__(16) int   d_dst[NE];
__device__ __align__(16) int   d_bat[NN];
__device__            int      d_flag64;
__device__ __align__(16) int   d_cnt[NN];
__device__ __align__(16) int   d_cursor[NN];
__device__ __align__(16) int   d_rowptr[NN + 1];
__device__ __align__(16) int   d_part[NSCB];
__device__ __align__(16) int   d_csrc[NE];
__device__ __align__(16) int   d_ceid[NE];
__device__ __align__(16) float d_xagg[NN * FIN];
__device__ __align__(16) float d_easum[NN * FE];
__device__ __align__(16) float d_deg[NN];
__device__ __align__(16) float d_h[(size_t)NN * HD];
__device__ __align__(16) float d_xlr[(size_t)NN * 2 * OD];
__device__ __align__(16) float d_gsum[NG * OD];
__device__ __align__(16) float d_gcnt[NG];
// split-bf16 weight images, [chunk][n=256][k=64]
__device__ __align__(16) __nv_bfloat16 d_B0h[3 * 16384];
__device__ __align__(16) __nv_bfloat16 d_B0l[3 * 16384];
__device__ __align__(16) __nv_bfloat16 d_B1h[4 * 16384];
__device__ __align__(16) __nv_bfloat16 d_B1l[4 * 16384];

// ---------------- helpers ----------------
__device__ __forceinline__ float gelu_t(float x) {
    float u = 0.7978845608028654f * (x + 0.044715f * x * x * x);
    return 0.5f * x * (1.0f + tanhf(u));
}

__device__ __forceinline__ void mma16816(float* c, const uint32_t* a, const uint32_t* b) {
    asm volatile(
        "mma.sync.aligned.m16n8k16.row.col.f32.bf16.bf16.f32 "
        "{%0,%1,%2,%3}, {%4,%5,%6,%7}, {%8,%9}, {%0,%1,%2,%3};"
        : "+f"(c[0]), "+f"(c[1]), "+f"(c[2]), "+f"(c[3])
        : "r"(a[0]), "r"(a[1]), "r"(a[2]), "r"(a[3]), "r"(b[0]), "r"(b[1]));
}

// ---------------- zero the small accumulators ----------------
__global__ void k_zero() {
    unsigned i = blockIdx.x * blockDim.x + threadIdx.x;
    unsigned st = gridDim.x * blockDim.x;
    for (unsigned j = i; j < NN; j += st) { d_cnt[j] = 0; d_cursor[j] = 0; }
    for (unsigned j = i; j < NG * OD; j += st) d_gsum[j] = 0.0f;
    for (unsigned j = i; j < NG; j += st) d_gcnt[j] = 0.0f;
}

// ---------------- index dtype sniff ----------------
__global__ void k_detect(const int* __restrict__ ei) {
    int allz = 1;
    for (int i = 1; i < 64; i += 2) if (ei[i] != 0) allz = 0;
    d_flag64 = allz;
}

// ---------------- convert indices + dst histogram ----------------
__global__ void k_convert(const int* __restrict__ ei, const int* __restrict__ bat) {
    int i = blockIdx.x * blockDim.x + threadIdx.x;
    int f = d_flag64;
    if (i < NE) {
        int s, d;
        if (f) { s = ei[2 * i]; d = ei[2 * (NE + i)]; }
        else   { s = ei[i];     d = ei[NE + i]; }
        d_src[i] = s; d_dst[i] = d;
        atomicAdd(&d_cnt[d], 1);
    }
    if (i < NN) d_bat[i] = f ? bat[2 * i] : bat[i];
}

// ---------------- multi-block exclusive scan ----------------
__global__ void k_scanA() {
    __shared__ int wsum[8];
    int t = threadIdx.x;
    int i = blockIdx.x * SCB + t;
    int v = (i < NN) ? d_cnt[i] : 0;
    int lane = t & 31, wid = t >> 5;
    int s = v;
#pragma unroll
    for (int o = 1; o < 32; o <<= 1) s += __shfl_xor_sync(0xFFFFFFFFu, s, o);
    if (lane == 0) wsum[wid] = s;
    __syncthreads();
    if (t == 0) {
        int r = 0;
#pragma unroll
        for (int k = 0; k < 8; k++) r += wsum[k];
        d_part[blockIdx.x] = r;
    }
}

__global__ void k_scanB() {
    __shared__ int s[NSCB];
    int t = threadIdx.x;
    if (t < NSCB) s[t] = d_part[t];
    __syncthreads();
    if (t == 0) {
        int r = 0;
        for (int k = 0; k < NSCB; k++) { int v = s[k]; s[k] = r; r += v; }
        d_rowptr[NN] = NE;
    }
    __syncthreads();
    if (t < NSCB) d_part[t] = s[t];
}

__global__ void k_scanC() {
    __shared__ int wsum[8];
    int t = threadIdx.x;
    int i = blockIdx.x * SCB + t;
    int v = (i < NN) ? d_cnt[i] : 0;
    int lane = t & 31, wid = t >> 5;
    int x = v;
#pragma unroll
    for (int o = 1; o < 32; o <<= 1) {
        int y = __shfl_up_sync(0xFFFFFFFFu, x, o);
        if (lane >= o) x += y;
    }
    if (lane == 31) wsum[wid] = x;
    __syncthreads();
    if (t == 0) {
        int r = 0;
#pragma unroll
        for (int k = 0; k < 8; k++) { int tmp = wsum[k]; wsum[k] = r; r += tmp; }
    }
    __syncthreads();
    if (i < NN) d_rowptr[i] = d_part[blockIdx.x] + wsum[wid] + x - v;
}

// ---------------- scatter edge ids into CSR order ----------------
__global__ void k_scatcsr() {
    int i = blockIdx.x * blockDim.x + threadIdx.x;
    if (i >= NE) return;
    int d = d_dst[i];
    int pos = d_rowptr[d] + atomicAdd(&d_cursor[d], 1);
    d_csrc[pos] = d_src[i];
    d_ceid[pos] = i;
}

// ---------------- layer-1 gather (warp per dst node) ----------
__global__ void k_gather(const float* __restrict__ x, const float* __restrict__ ea) {
    int w = (blockIdx.x * blockDim.x + threadIdx.x) >> 5;
    if (w >= NN) return;
    int lane = threadIdx.x & 31;
    int b = d_rowptr[w], e = d_rowptr[w + 1];
    float2 xs = make_float2(0.f, 0.f);
    float es = 0.f;
    for (int i = b; i < e; i++) {
        int s = d_csrc[i];
        float2 v = __ldg((const float2*)(x + (size_t)s * FIN) + lane);
        xs.x += v.x; xs.y += v.y;
        if (lane < FE) {
            int eid = d_ceid[i];
            es += __ldg(ea + (size_t)eid * FE + lane);
        }
    }
    ((float2*)(d_xagg + (size_t)w * FIN))[lane] = xs;
    if (lane < FE) d_easum[w * FE + lane] = es;
    if (lane == 0) d_deg[w] = (float)(e - b);
}

// ------- prep: transpose + split(hi/lo) weight images [c][n][k] ----------
__global__ void k_prepw(const float* __restrict__ Wmsg, const float* __restrict__ Wself,
                        const float* __restrict__ We1, const float* __restrict__ Wl,
                        const float* __restrict__ Wr) {
    int i = blockIdx.x * blockDim.x + threadIdx.x;
    if (i < 3 * 16384) {
        int c = i >> 14, rem = i & 16383;
        int n = rem >> 6, kk = rem & 63, k = c * 64 + kk;
        float v = 0.f;
        if (k < 64)       v = Wmsg[k * 256 + n];
        else if (k < 128) v = Wself[(k - 64) * 256 + n];
        else if (k < 144) v = We1[(k - 128) * 256 + n];
        __nv_bfloat16 h = __float2bfloat16(v);
        __nv_bfloat16 l = __float2bfloat16(v - __bfloat162float(h));
        d_B0h[i] = h; d_B0l[i] = l;
    }
    if (i < 4 * 16384) {
        int c = i >> 14, rem = i & 16383;
        int n = rem >> 6, kk = rem & 63, k = c * 64 + kk;
        float v = (n < 128) ? Wl[k * 128 + n] : Wr[k * 128 + (n - 128)];
        __nv_bfloat16 h = __float2bfloat16(v);
        __nv_bfloat16 l = __float2bfloat16(v - __bfloat162float(h));
        d_B1h[i] = h; d_B1l[i] = l;
    }
}

// ---------------- split-bf16 GEMM via mma.sync (legacy tensor path) -------
// MODE 0: d_h   = gelu([xagg|x|easum] @ W0 + deg*(bm+be1) + bs), K=144
// MODE 1: d_xlr = d_h @ [Wl|Wr] + [bl|br], K=256
// CTA: 256 thr / 8 warps; tile M=128 N=64; warp tile 32x32; K chunks of 64.
// 3-term split: D += Ah*Bh + Ah*Bl + Al*Bh  (fp32 accum)
#define SAS 72   // smem k-stride (bf16 units)
template <int MODE>
__global__ void __launch_bounds__(256)
k_gemm(const float* __restrict__ x, const float* __restrict__ bm,
       const float* __restrict__ be1, const float* __restrict__ bs,
       const float* __restrict__ bl, const float* __restrict__ br) {
    constexpr int NCH = (MODE == 0) ? 3 : 4;
    extern __shared__ __align__(16) char smem[];
    __nv_bfloat16* sAh = (__nv_bfloat16*)smem;        // 128*SAS
    __nv_bfloat16* sAl = sAh + 128 * SAS;
    __nv_bfloat16* sBh = sAl + 128 * SAS;             // 64*SAS
    __nv_bfloat16* sBl = sBh + 64 * SAS;

    const int tid = threadIdx.x;
    const int lane = tid & 31, wid = tid >> 5;
    const int wm = wid & 3, wn = wid >> 2;
    const int q = lane >> 2, rr = (lane & 3) * 2;
    const int r0 = blockIdx.x * 128, c0 = blockIdx.y * 64;
    const __nv_bfloat16* Bh_g = (MODE == 0) ? d_B0h : d_B1h;
    const __nv_bfloat16* Bl_g = (MODE == 0) ? d_B0l : d_B1l;

    float acc[2][4][4];
#pragma unroll
    for (int a = 0; a < 2; a++)
#pragma unroll
        for (int b = 0; b < 4; b++)
#pragma unroll
            for (int u = 0; u < 4; u++) acc[a][b][u] = 0.0f;

    for (int c = 0; c < NCH; c++) {
        __syncthreads();
        // stage A: fp32 -> split bf16 hi/lo
        for (int i = tid; i < 4096; i += 256) {
            int r = i >> 5, p = i & 31;
            int row = r0 + r; if (row >= NN) row = NN - 1;
            float2 v;
            if (MODE == 0) {
                if (c == 0)      v = *(const float2*)(d_xagg + (size_t)row * 64 + 2 * p);
                else if (c == 1) v = *(const float2*)(x + (size_t)row * 64 + 2 * p);
                else             v = (p < 8) ? *(const float2*)(d_easum + (size_t)row * 16 + 2 * p)
                                             : make_float2(0.f, 0.f);
            } else {
                v = *(const float2*)(d_h + (size_t)row * 256 + c * 64 + 2 * p);
            }
            __nv_bfloat16 h0 = __float2bfloat16(v.x);
            __nv_bfloat16 h1 = __float2bfloat16(v.y);
            __nv_bfloat16 l0 = __float2bfloat16(v.x - __bfloat162float(h0));
            __nv_bfloat16 l1 = __float2bfloat16(v.y - __bfloat162float(h1));
            uint32_t hp = (uint32_t)__bfloat16_as_ushort(h0) |
                          ((uint32_t)__bfloat16_as_ushort(h1) << 16);
            uint32_t lp = (uint32_t)__bfloat16_as_ushort(l0) |
                          ((uint32_t)__bfloat16_as_ushort(l1) << 16);
            *(uint32_t*)&sAh[r * SAS + 2 * p] = hp;
            *(uint32_t*)&sAl[r * SAS + 2 * p] = lp;
        }
        // stage B: copy pre-split images (this CTA's 64 n-rows)
        for (int i = tid; i < 2048; i += 256) {
            int nr = i >> 5, p = i & 31;
            size_t go = (size_t)c * 16384 + (size_t)(c0 + nr) * 64 + 2 * p;
            *(uint32_t*)&sBh[nr * SAS + 2 * p] = *(const uint32_t*)(Bh_g + go);
            *(uint32_t*)&sBl[nr * SAS + 2 * p] = *(const uint32_t*)(Bl_g + go);
        }
        __syncthreads();

        const int nsteps = (MODE == 0 && c == 2) ? 1 : 4;
        for (int ks = 0; ks < nsteps; ks++) {
            int kc = ks * 16 + rr;
            uint32_t ah[2][4], al[2][4], bh[4][2], blo[4][2];
#pragma unroll
            for (int mt = 0; mt < 2; mt++) {
                int ra = wm * 32 + mt * 16 + q;
                ah[mt][0] = *(uint32_t*)&sAh[ra * SAS + kc];
                ah[mt][1] = *(uint32_t*)&sAh[(ra + 8) * SAS + kc];
                ah[mt][2] = *(uint32_t*)&sAh[ra * SAS + kc + 8];
                ah[mt][3] = *(uint32_t*)&sAh[(ra + 8) * SAS + kc + 8];
                al[mt][0] = *(uint32_t*)&sAl[ra * SAS + kc];
                al[mt][1] = *(uint32_t*)&sAl[(ra + 8) * SAS + kc];
                al[mt][2] = *(uint32_t*)&sAl[ra * SAS + kc + 8];
                al[mt][3] = *(uint32_t*)&sAl[(ra + 8) * SAS + kc + 8];
            }
#pragma unroll
            for (int nt = 0; nt < 4; nt++) {
                int nb = wn * 32 + nt * 8 + q;
                bh[nt][0] = *(uint32_t*)&sBh[nb * SAS + kc];
                bh[nt][1] = *(uint32_t*)&sBh[nb * SAS + kc + 8];
                blo[nt][0] = *(uint32_t*)&sBl[nb * SAS + kc];
                blo[nt][1] = *(uint32_t*)&sBl[nb * SAS + kc + 8];
            }
#pragma unroll
            for (int mt = 0; mt < 2; mt++)
#pragma unroll
                for (int nt = 0; nt < 4; nt++) {
                    mma16816(acc[mt][nt], ah[mt], bh[nt]);
                    mma16816(acc[mt][nt], ah[mt], blo[nt]);
                    mma16816(acc[mt][nt], al[mt], bh[nt]);
                }
        }
    }

    // epilogue: fragment -> global with bias/gelu fusion
    float* C = (MODE == 0) ? d_h : d_xlr;
#pragma unroll
    for (int mt = 0; mt < 2; mt++) {
        int row0 = r0 + wm * 32 + mt * 16 + q;
#pragma unroll
        for (int nt = 0; nt < 4; nt++) {
            int cc = c0 + wn * 32 + nt * 8 + rr;
            float b0, b1, s0, s1;
            if (MODE == 0) {
                b0 = bm[cc] + be1[cc]; b1 = bm[cc + 1] + be1[cc + 1];
                s0 = bs[cc]; s1 = bs[cc + 1];
            } else {
                b0 = b1 = 0.f;
                s0 = (cc < 128) ? bl[cc] : br[cc - 128];
                s1 = (cc + 1 < 128) ? bl[cc + 1] : br[cc + 1 - 128];
            }
#pragma unroll
            for (int h = 0; h < 2; h++) {
                int row = row0 + h * 8;
                if (row < NN) {
                    float v0 = acc[mt][nt][2 * h + 0];
                    float v1 = acc[mt][nt][2 * h + 1];
                    if (MODE == 0) {
                        float dg = d_deg[row];
                        v0 = gelu_t(v0 + dg * b0 + s0);
                        v1 = gelu_t(v1 + dg * b1 + s1);
                    } else {
                        v0 += s0; v1 += s1;
                    }
                    *(float2*)(&C[(size_t)row * 256 + cc]) = make_float2(v0, v1);
                }
            }
        }
    }
}

// ------- fused GATv2 attention + pool, ONLINE softmax (warp per node) -----
__global__ void __launch_bounds__(256)
k_att(const float* __restrict__ ea, const float* __restrict__ We2,
      const float* __restrict__ att, const float* __restrict__ bias2) {
    __shared__ float sW[FE * OD];
    __shared__ float sA[OD];
    for (int i = threadIdx.x; i < FE * OD; i += 256) sW[i] = We2[i];
    for (int i = threadIdx.x; i < OD; i += 256) sA[i] = att[i];
    __syncthreads();

    int w = (blockIdx.x * blockDim.x + threadIdx.x) >> 5;
    if (w >= NN) return;
    int lane = threadIdx.x & 31;
    int k0 = lane * 4;
    int b = d_rowptr[w], e = d_rowptr[w + 1];
    float degf = (float)(e - b);
    float inv_deg = 1.0f / fmaxf(degf, 1.0f);

    float4 vr  = *(const float4*)(d_xlr + (size_t)w * 256 + 128 + k0);
    float4 sAv = *(const float4*)(&sA[k0]);

    float amax = -1e30f;
    float denom = 0.0f;
    float4 out = make_float4(0.f, 0.f, 0.f, 0.f);

    for (int i = b; i <= e; i++) {
        int s;
        float ear[FE];
        if (i < e) {
            s = d_csrc[i];
            int eid = d_ceid[i];
            const float4* p4 = (const float4*)(ea + (size_t)eid * FE);
#pragma unroll
            for (int qq = 0; qq < 4; qq++) {
                float4 ev = __ldg(p4 + qq);
                ear[qq * 4 + 0] = ev.x; ear[qq * 4 + 1] = ev.y;
                ear[qq * 4 + 2] = ev.z; ear[qq * 4 + 3] = ev.w;
            }
        } else {
            s = w;
            const float4* p4 = (const float4*)(d_easum + (size_t)w * FE);
#pragma unroll
            for (int qq = 0; qq < 4; qq++) {
                float4 ev = p4[qq];
                ear[qq * 4 + 0] = ev.x * inv_deg; ear[qq * 4 + 1] = ev.y * inv_deg;
                ear[qq * 4 + 2] = ev.z * inv_deg; ear[qq * 4 + 3] = ev.w * inv_deg;
            }
        }
        float4 xl = *(const float4*)(d_xlr + (size_t)s * 256 + k0);
        float m0 = xl.x + vr.x, m1 = xl.y + vr.y, m2 = xl.z + vr.z, m3 = xl.w + vr.w;
#pragma unroll
        for (int qq = 0; qq < FE; qq++) {
            float ev = ear[qq];
            float4 wv = *(const float4*)(&sW[qq * OD + k0]);
            m0 = fmaf(ev, wv.x, m0); m1 = fmaf(ev, wv.y, m1);
            m2 = fmaf(ev, wv.z, m2); m3 = fmaf(ev, wv.w, m3);
        }
        m0 = m0 > 0.f ? m0 : 0.2f * m0;
        m1 = m1 > 0.f ? m1 : 0.2f * m1;
        m2 = m2 > 0.f ? m2 : 0.2f * m2;
        m3 = m3 > 0.f ? m3 : 0.2f * m3;
        float a = m0 * sAv.x + m1 * sAv.y + m2 * sAv.z + m3 * sAv.w;
#pragma unroll
        for (int o = 16; o; o >>= 1) a += __shfl_xor_sync(0xFFFFFFFFu, a, o);

        float ev;
        if (a > amax) {
            float cc = __expf(amax - a);
            denom *= cc;
            out.x *= cc; out.y *= cc; out.z *= cc; out.w *= cc;
            amax = a;
            ev = 1.0f;
        } else {
            ev = __expf(a - amax);
        }
        denom += ev;
        out.x = fmaf(ev, xl.x, out.x); out.y = fmaf(ev, xl.y, out.y);
        out.z = fmaf(ev, xl.z, out.z); out.w = fmaf(ev, xl.w, out.w);
    }

    float invd = 1.0f / denom;
    float4 bb = *(const float4*)(bias2 + k0);
    out.x = fmaf(out.x, invd, bb.x); out.y = fmaf(out.y, invd, bb.y);
    out.z = fmaf(out.z, invd, bb.z); out.w = fmaf(out.w, invd, bb.w);

    int g = d_bat[w];
    atomicAdd((float4*)(d_gsum + (size_t)g * OD) + lane, out);
    if (lane == 0) atomicAdd(&d_gcnt[g], 1.0f);
}

// ---------------- FFN head ----------------
__global__ void k_ffn(const float* __restrict__ W1, const float* __restrict__ b1,
                      const float* __restrict__ W2, const float* __restrict__ b2,
                      float* __restrict__ y) {
    __shared__ float g[OD];
    __shared__ float red[128];
    int b = blockIdx.x, t = threadIdx.x;
    float inv = 1.0f / fmaxf(d_gcnt[b], 1.0f);
    g[t] = d_gsum[b * OD + t] * inv;
    __syncthreads();
    float part = 0.0f;
#pragma unroll
    for (int q = 0; q < 4; q++) {
        int j = t + q * 128;
        float acc = b1[j];
        for (int k = 0; k < OD; k++) acc = fmaf(g[k], W1[k * 512 + j], acc);
        part = fmaf(gelu_t(acc), W2[j], part);
    }
    red[t] = part;
    __syncthreads();
    for (int o = 64; o; o >>= 1) {
        if (t < o) red[t] += red[t + o];
        __syncthreads();
    }
    if (t == 0) y[b] = red[0] + b2[0];
}

// ---------------- launch ----------------
static int g_attr_done = 0;

extern "C" void kernel_launch(void* const* d_in, const int* in_sizes, int n_in,
                              void* d_out, int out_size) {
    (void)in_sizes; (void)n_in; (void)out_size;
    const float* x     = (const float*)d_in[0];
    const int*   ei    = (const int*)d_in[1];
    const float* ea    = (const float*)d_in[2];
    const int*   bat   = (const int*)d_in[3];
    const float* Wmsg  = (const float*)d_in[4];
    const float* bmsg  = (const float*)d_in[5];
    const float* We1   = (const float*)d_in[6];
    const float* be1   = (const float*)d_in[7];
    const float* Wself = (const float*)d_in[8];
    const float* bself = (const float*)d_in[9];
    const float* Wl    = (const float*)d_in[10];
    const float* bl    = (const float*)d_in[11];
    const float* Wr    = (const float*)d_in[12];
    const float* br    = (const float*)d_in[13];
    const float* We2   = (const float*)d_in[14];
    const float* att   = (const float*)d_in[15];
    const float* bias2 = (const float*)d_in[16];
    const float* W1    = (const float*)d_in[17];
    const float* b1    = (const float*)d_in[18];
    const float* W2    = (const float*)d_in[19];
    const float* b2    = (const float*)d_in[20];
    float* y = (float*)d_out;

    if (!g_attr_done) {
        cudaFuncSetAttribute(k_gemm<0>, cudaFuncAttributeMaxDynamicSharedMemorySize, SMEMSZ);
        cudaFuncSetAttribute(k_gemm<1>, cudaFuncAttributeMaxDynamicSharedMemorySize, SMEMSZ);
        g_attr_done = 1;
    }

    k_zero<<<512, 256>>>();
    k_detect<<<1, 1>>>(ei);
    k_convert<<<(NE + 255) / 256, 256>>>(ei, bat);
    k_scanA<<<NSCB, SCB>>>();
    k_scanB<<<1, 256>>>();
    k_scanC<<<NSCB, SCB>>>();
    k_scatcsr<<<(NE + 255) / 256, 256>>>();
    k_gather<<<NN / 8, 256>>>(x, ea);
    k_prepw<<<256, 256>>>(Wmsg, Wself, We1, Wl, Wr);
    dim3 gg((NN + 127) / 128, 4);
    k_gemm<0><<<gg, 256, SMEMSZ>>>(x, bmsg, be1, bself, nullptr, nullptr);
    k_gemm<1><<<gg, 256, SMEMSZ>>>(x, nullptr, nullptr, nullptr, bl, br);
    k_att<<<NN / 8, 256>>>(ea, We2, att, bias2);
    k_ffn<<<NG, 128>>>(W1, b1, W2, b2, y);
}

// round 15
// speedup vs baseline: 1.4419x; 1.4419x over previous
#include <cuda_runtime.h>
#include <math.h>
#include <stdint.h>

#define NN 40000
#define NE 640000
#define FIN 64
#define FE 16
#define NG 1000
#define HD 256
#define OD 128

#define SCB 256
#define NSCB ((NN + SCB - 1) / SCB)   // 157

// ---------------- scratch (device globals) ----------------
__device__ __align__(16) int   d_src[NE];
__device__ __align__(16) int   d_dst[NE];
__device__ __align__(16) int   d_bat[NN];
__device__            int      d_flag64;
__device__ __align__(16) int   d_cnt[NN];
__device__ __align__(16) int   d_cursor[NN];
__device__ __align__(16) int   d_rowptr[NN + 1];
__device__ __align__(16) int   d_part[NSCB];
__device__ __align__(16) int   d_csrc[NE];
__device__ __align__(16) int   d_ceid[NE];
__device__ __align__(16) float d_xagg[NN * FIN];
__device__ __align__(16) float d_easum[NN * FE];
__device__ __align__(16) float d_deg[NN];
__device__ __align__(16) float d_Wcat[144 * HD];
__device__ __align__(16) float d_h[(size_t)NN * HD];
__device__ __align__(16) float d_Wlr[HD * 2 * OD];
__device__ __align__(16) float d_blr[2 * OD];
__device__ __align__(16) float d_xlr[(size_t)NN * 2 * OD];
__device__ __align__(16) float d_gsum[NG * OD];
__device__ __align__(16) float d_gcnt[NG];

// ---------------- helpers ----------------
__device__ __forceinline__ float gelu_t(float x) {
    float u = 0.7978845608028654f * (x + 0.044715f * x * x * x);
    return 0.5f * x * (1.0f + tanhf(u));
}

// ---------------- zero accumulators + index dtype sniff ----------------
__global__ void k_zero(const int* __restrict__ ei) {
    unsigned i = blockIdx.x * blockDim.x + threadIdx.x;
    unsigned st = gridDim.x * blockDim.x;
    for (unsigned j = i; j < NN; j += st) { d_cnt[j] = 0; d_cursor[j] = 0; }
    for (unsigned j = i; j < NG * OD; j += st) d_gsum[j] = 0.0f;
    for (unsigned j = i; j < NG; j += st) d_gcnt[j] = 0.0f;
    if (i == 0) {
        int allz = 1;
        for (int k = 1; k < 64; k += 2) if (ei[k] != 0) allz = 0;
        d_flag64 = allz;
    }
}

// ---------------- convert indices + dst histogram ----------------
__global__ void k_convert(const int* __restrict__ ei, const int* __restrict__ bat) {
    int i = blockIdx.x * blockDim.x + threadIdx.x;
    int f = d_flag64;
    if (i < NE) {
        int s, d;
        if (f) { s = ei[2 * i]; d = ei[2 * (NE + i)]; }
        else   { s = ei[i];     d = ei[NE + i]; }
        d_src[i] = s; d_dst[i] = d;
        atomicAdd(&d_cnt[d], 1);
    }
    if (i < NN) d_bat[i] = f ? bat[2 * i] : bat[i];
}

// ---------------- multi-block exclusive scan ----------------
__global__ void k_scanA() {
    __shared__ int wsum[8];
    int t = threadIdx.x;
    int i = blockIdx.x * SCB + t;
    int v = (i < NN) ? d_cnt[i] : 0;
    int lane = t & 31, wid = t >> 5;
    int s = v;
#pragma unroll
    for (int o = 1; o < 32; o <<= 1) s += __shfl_xor_sync(0xFFFFFFFFu, s, o);
    if (lane == 0) wsum[wid] = s;
    __syncthreads();
    if (t == 0) {
        int r = 0;
#pragma unroll
        for (int k = 0; k < 8; k++) r += wsum[k];
        d_part[blockIdx.x] = r;
    }
}

__global__ void k_scanB() {
    __shared__ int s[NSCB];
    int t = threadIdx.x;
    if (t < NSCB) s[t] = d_part[t];
    __syncthreads();
    if (t == 0) {
        int r = 0;
        for (int k = 0; k < NSCB; k++) { int v = s[k]; s[k] = r; r += v; }
        d_rowptr[NN] = NE;
    }
    __syncthreads();
    if (t < NSCB) d_part[t] = s[t];
}

__global__ void k_scanC() {
    __shared__ int wsum[8];
    int t = threadIdx.x;
    int i = blockIdx.x * SCB + t;
    int v = (i < NN) ? d_cnt[i] : 0;
    int lane = t & 31, wid = t >> 5;
    int x = v;
#pragma unroll
    for (int o = 1; o < 32; o <<= 1) {
        int y = __shfl_up_sync(0xFFFFFFFFu, x, o);
        if (lane >= o) x += y;
    }
    if (lane == 31) wsum[wid] = x;
    __syncthreads();
    if (t == 0) {
        int r = 0;
#pragma unroll
        for (int k = 0; k < 8; k++) { int tmp = wsum[k]; wsum[k] = r; r += tmp; }
    }
    __syncthreads();
    if (i < NN) d_rowptr[i] = d_part[blockIdx.x] + wsum[wid] + x - v;
}

// ---------------- scatter edge ids into CSR order ----------------
__global__ void k_scatcsr() {
    int i = blockIdx.x * blockDim.x + threadIdx.x;
    if (i >= NE) return;
    int d = d_dst[i];
    int pos = d_rowptr[d] + atomicAdd(&d_cursor[d], 1);
    d_csrc[pos] = d_src[i];
    d_ceid[pos] = i;
}

// ---------------- layer-1 gather (warp per dst node, 4-way MLP) ----------
__global__ void k_gather(const float* __restrict__ x, const float* __restrict__ ea) {
    int w = (blockIdx.x * blockDim.x + threadIdx.x) >> 5;
    if (w >= NN) return;
    int lane = threadIdx.x & 31;
    int b = d_rowptr[w], e = d_rowptr[w + 1];
    float2 xs = make_float2(0.f, 0.f);
    float es = 0.f;
    int i = b;
    for (; i + 3 < e; i += 4) {
        int s0 = d_csrc[i], s1 = d_csrc[i + 1], s2 = d_csrc[i + 2], s3 = d_csrc[i + 3];
        float2 v0 = __ldg((const float2*)(x + (size_t)s0 * FIN) + lane);
        float2 v1 = __ldg((const float2*)(x + (size_t)s1 * FIN) + lane);
        float2 v2 = __ldg((const float2*)(x + (size_t)s2 * FIN) + lane);
        float2 v3 = __ldg((const float2*)(x + (size_t)s3 * FIN) + lane);
        xs.x += (v0.x + v1.x) + (v2.x + v3.x);
        xs.y += (v0.y + v1.y) + (v2.y + v3.y);
        if (lane < FE) {
            float e0 = __ldg(ea + (size_t)d_ceid[i] * FE + lane);
            float e1 = __ldg(ea + (size_t)d_ceid[i + 1] * FE + lane);
            float e2 = __ldg(ea + (size_t)d_ceid[i + 2] * FE + lane);
            float e3 = __ldg(ea + (size_t)d_ceid[i + 3] * FE + lane);
            es += (e0 + e1) + (e2 + e3);
        }
    }
    for (; i < e; i++) {
        int s = d_csrc[i];
        float2 v = __ldg((const float2*)(x + (size_t)s * FIN) + lane);
        xs.x += v.x; xs.y += v.y;
        if (lane < FE) es += __ldg(ea + (size_t)d_ceid[i] * FE + lane);
    }
    ((float2*)(d_xagg + (size_t)w * FIN))[lane] = xs;
    if (lane < FE) d_easum[w * FE + lane] = es;
    if (lane == 0) d_deg[w] = (float)(e - b);
}

// ---------------- pack fused weights (float4) ----------------
__global__ void k_packw(const float* __restrict__ Wmsg, const float* __restrict__ Wself,
                        const float* __restrict__ We1, const float* __restrict__ Wl,
                        const float* __restrict__ bl, const float* __restrict__ Wr,
                        const float* __restrict__ br) {
    int i = blockIdx.x * blockDim.x + threadIdx.x;   // float4 index
    if (i < 4096)       ((float4*)d_Wcat)[i] = ((const float4*)Wmsg)[i];
    else if (i < 8192)  ((float4*)d_Wcat)[i] = ((const float4*)Wself)[i - 4096];
    else if (i < 9216)  ((float4*)d_Wcat)[i] = ((const float4*)We1)[i - 8192];
    if (i < 16384) {
        int k = i >> 6, c4 = i & 63;
        ((float4*)d_Wlr)[i] = (c4 < 32) ? ((const float4*)Wl)[k * 32 + c4]
                                        : ((const float4*)Wr)[k * 32 + (c4 - 32)];
    }
    if (i < 64) ((float4*)d_blr)[i] = (i < 32) ? ((const float4*)bl)[i]
                                               : ((const float4*)br)[i - 32];
}

// ---------------- fp32 SGEMM: 128x64 tile, 256 thr, 8x4 micro, dbl-buffer --
template <int MODE>
__global__ void __launch_bounds__(256, 3)
k_gemm(const float* __restrict__ x, const float* __restrict__ bm,
       const float* __restrict__ be1, const float* __restrict__ bs) {
    constexpr int K = (MODE == 0) ? 144 : 256;
    __shared__ float As[2][16][132];
    __shared__ float Bs[2][16][64];
    const float* B = (MODE == 0) ? d_Wcat : d_Wlr;
    float* C       = (MODE == 0) ? d_h : d_xlr;

    const int r0 = blockIdx.x * 128, c0 = blockIdx.y * 64;
    const int t = threadIdx.x;
    const int tx = t & 15, ty = t >> 4;

    const int ar = t >> 1;
    const int ak = (t & 1) * 4;
    int arow = r0 + ar; if (arow >= NN) arow = NN - 1;
    const int brw = t >> 4;
    const int bc = (t & 15) * 4;

    float acc[8][4];
#pragma unroll
    for (int i = 0; i < 8; i++)
#pragma unroll
        for (int j = 0; j < 4; j++) acc[i][j] = 0.0f;

    float4 a0, a1, b0;
    auto fetchA = [&](int kt, float4& u0, float4& u1) {
        const float* p;
        int k = kt + ak;
        if (MODE == 0) {
            if (k < 64)       p = d_xagg + (size_t)arow * 64 + k;
            else if (k < 128) p = x + (size_t)arow * 64 + (k - 64);
            else              p = d_easum + (size_t)arow * 16 + (k - 128);
        } else {
            p = d_h + (size_t)arow * 256 + k;
        }
        u0 = *(const float4*)p;
        u1 = *(const float4*)(p + 8);
    };
    auto stageA = [&](int buf, const float4& u0, const float4& u1) {
        As[buf][ak + 0][ar] = u0.x; As[buf][ak + 1][ar] = u0.y;
        As[buf][ak + 2][ar] = u0.z; As[buf][ak + 3][ar] = u0.w;
        As[buf][ak + 8][ar] = u1.x; As[buf][ak + 9][ar] = u1.y;
        As[buf][ak + 10][ar] = u1.z; As[buf][ak + 11][ar] = u1.w;
    };

    fetchA(0, a0, a1);
    b0 = *(const float4*)(B + (size_t)brw * 256 + c0 + bc);
    stageA(0, a0, a1);
    *(float4*)(&Bs[0][brw][bc]) = b0;
    __syncthreads();

    int buf = 0;
    for (int kt = 16; kt < K; kt += 16) {
        fetchA(kt, a0, a1);
        b0 = *(const float4*)(B + (size_t)(kt + brw) * 256 + c0 + bc);
#pragma unroll
        for (int kk = 0; kk < 16; kk++) {
            float4 av0 = *(const float4*)(&As[buf][kk][ty * 8]);
            float4 av1 = *(const float4*)(&As[buf][kk][ty * 8 + 4]);
            float4 bv  = *(const float4*)(&Bs[buf][kk][tx * 4]);
            float arr[8] = {av0.x, av0.y, av0.z, av0.w, av1.x, av1.y, av1.z, av1.w};
            float brr[4] = {bv.x, bv.y, bv.z, bv.w};
#pragma unroll
            for (int i = 0; i < 8; i++)
#pragma unroll
                for (int j = 0; j < 4; j++)
                    acc[i][j] = fmaf(arr[i], brr[j], acc[i][j]);
        }
        buf ^= 1;
        stageA(buf, a0, a1);
        *(float4*)(&Bs[buf][brw][bc]) = b0;
        __syncthreads();
    }
#pragma unroll
    for (int kk = 0; kk < 16; kk++) {
        float4 av0 = *(const float4*)(&As[buf][kk][ty * 8]);
        float4 av1 = *(const float4*)(&As[buf][kk][ty * 8 + 4]);
        float4 bv  = *(const float4*)(&Bs[buf][kk][tx * 4]);
        float arr[8] = {av0.x, av0.y, av0.z, av0.w, av1.x, av1.y, av1.z, av1.w};
        float brr[4] = {bv.x, bv.y, bv.z, bv.w};
#pragma unroll
        for (int i = 0; i < 8; i++)
#pragma unroll
            for (int j = 0; j < 4; j++)
                acc[i][j] = fmaf(arr[i], brr[j], acc[i][j]);
    }

    float cb[4], sb[4];
#pragma unroll
    for (int j = 0; j < 4; j++) {
        int col = c0 + tx * 4 + j;
        if (MODE == 0) { cb[j] = bm[col] + be1[col]; sb[j] = bs[col]; }
        else           { cb[j] = 0.0f;               sb[j] = d_blr[col]; }
    }
#pragma unroll
    for (int i = 0; i < 8; i++) {
        int row = r0 + ty * 8 + i;
        if (row < NN) {
            float dg = (MODE == 0) ? d_deg[row] : 0.0f;
            float v0 = acc[i][0] + dg * cb[0] + sb[0];
            float v1 = acc[i][1] + dg * cb[1] + sb[1];
            float v2 = acc[i][2] + dg * cb[2] + sb[2];
            float v3 = acc[i][3] + dg * cb[3] + sb[3];
            float4 o;
            if (MODE == 0) o = make_float4(gelu_t(v0), gelu_t(v1), gelu_t(v2), gelu_t(v3));
            else           o = make_float4(v0, v1, v2, v3);
            *(float4*)(&C[(size_t)row * 256 + c0 + tx * 4]) = o;
        }
    }
}

// ------- fused GATv2 attention + pool, online softmax + SW pipeline -------
__global__ void __launch_bounds__(256)
k_att(const float* __restrict__ ea, const float* __restrict__ We2,
      const float* __restrict__ att, const float* __restrict__ bias2) {
    __shared__ float sW[FE * OD];
    __shared__ float sA[OD];
    for (int i = threadIdx.x; i < FE * OD; i += 256) sW[i] = We2[i];
    for (int i = threadIdx.x; i < OD; i += 256) sA[i] = att[i];
    __syncthreads();

    int w = (blockIdx.x * blockDim.x + threadIdx.x) >> 5;
    if (w >= NN) return;
    int lane = threadIdx.x & 31;
    int k0 = lane * 4;
    int b = d_rowptr[w], e = d_rowptr[w + 1];
    float degf = (float)(e - b);
    float inv_deg = 1.0f / fmaxf(degf, 1.0f);

    float4 vr  = *(const float4*)(d_xlr + (size_t)w * 256 + 128 + k0);
    float4 sAv = *(const float4*)(&sA[k0]);
    float4 xlw = *(const float4*)(d_xlr + (size_t)w * 256 + k0);

    // --- self-loop first (branch-free hot loop afterwards) ---
    float amax, denom;
    float4 out;
    {
        float4 ec[4];
        const float4* p4 = (const float4*)(d_easum + (size_t)w * FE);
#pragma unroll
        for (int q = 0; q < 4; q++) {
            float4 ev = p4[q];
            ec[q] = make_float4(ev.x * inv_deg, ev.y * inv_deg,
                                ev.z * inv_deg, ev.w * inv_deg);
        }
        float m0 = xlw.x + vr.x, m1 = xlw.y + vr.y, m2 = xlw.z + vr.z, m3 = xlw.w + vr.w;
#pragma unroll
        for (int q4 = 0; q4 < 4; q4++) {
            float4 E = ec[q4];
            const float* wp = &sW[(q4 * 4) * OD + k0];
            float4 wa = *(const float4*)(wp);
            float4 wb = *(const float4*)(wp + OD);
            float4 wc = *(const float4*)(wp + 2 * OD);
            float4 wd = *(const float4*)(wp + 3 * OD);
            m0 = fmaf(E.x, wa.x, fmaf(E.y, wb.x, fmaf(E.z, wc.x, fmaf(E.w, wd.x, m0))));
            m1 = fmaf(E.x, wa.y, fmaf(E.y, wb.y, fmaf(E.z, wc.y, fmaf(E.w, wd.y, m1))));
            m2 = fmaf(E.x, wa.z, fmaf(E.y, wb.z, fmaf(E.z, wc.z, fmaf(E.w, wd.z, m2))));
            m3 = fmaf(E.x, wa.w, fmaf(E.y, wb.w, fmaf(E.z, wc.w, fmaf(E.w, wd.w, m3))));
        }
        m0 = m0 > 0.f ? m0 : 0.2f * m0;
        m1 = m1 > 0.f ? m1 : 0.2f * m1;
        m2 = m2 > 0.f ? m2 : 0.2f * m2;
        m3 = m3 > 0.f ? m3 : 0.2f * m3;
        float a = m0 * sAv.x + m1 * sAv.y + m2 * sAv.z + m3 * sAv.w;
#pragma unroll
        for (int o = 16; o; o >>= 1) a += __shfl_xor_sync(0xFFFFFFFFu, a, o);
        amax = a;
        denom = 1.0f;
        out = xlw;
    }

    // --- plain edges, software-pipelined (prefetch i+1 while computing i) ---
    float4 ec0 = make_float4(0, 0, 0, 0), ec1 = ec0, ec2 = ec0, ec3 = ec0;
    float4 xl_c = ec0;
    if (b < e) {
        int s = d_csrc[b];
        const float4* p4 = (const float4*)(ea + (size_t)d_ceid[b] * FE);
        ec0 = __ldg(p4 + 0); ec1 = __ldg(p4 + 1);
        ec2 = __ldg(p4 + 2); ec3 = __ldg(p4 + 3);
        xl_c = *(const float4*)(d_xlr + (size_t)s * 256 + k0);
    }
    for (int i = b; i < e; i++) {
        float4 en0, en1, en2, en3, xl_n;
        if (i + 1 < e) {
            int sn = d_csrc[i + 1];
            const float4* p4 = (const float4*)(ea + (size_t)d_ceid[i + 1] * FE);
            en0 = __ldg(p4 + 0); en1 = __ldg(p4 + 1);
            en2 = __ldg(p4 + 2); en3 = __ldg(p4 + 3);
            xl_n = *(const float4*)(d_xlr + (size_t)sn * 256 + k0);
        } else {
            en0 = en1 = en2 = en3 = xl_n = make_float4(0, 0, 0, 0);
        }

        float m0 = xl_c.x + vr.x, m1 = xl_c.y + vr.y;
        float m2 = xl_c.z + vr.z, m3 = xl_c.w + vr.w;
        float4 EE[4] = {ec0, ec1, ec2, ec3};
#pragma unroll
        for (int q4 = 0; q4 < 4; q4++) {
            float4 E = EE[q4];
            const float* wp = &sW[(q4 * 4) * OD + k0];
            float4 wa = *(const float4*)(wp);
            float4 wb = *(const float4*)(wp + OD);
            float4 wc = *(const float4*)(wp + 2 * OD);
            float4 wd = *(const float4*)(wp + 3 * OD);
            m0 = fmaf(E.x, wa.x, fmaf(E.y, wb.x, fmaf(E.z, wc.x, fmaf(E.w, wd.x, m0))));
            m1 = fmaf(E.x, wa.y, fmaf(E.y, wb.y, fmaf(E.z, wc.y, fmaf(E.w, wd.y, m1))));
            m2 = fmaf(E.x, wa.z, fmaf(E.y, wb.z, fmaf(E.z, wc.z, fmaf(E.w, wd.z, m2))));
            m3 = fmaf(E.x, wa.w, fmaf(E.y, wb.w, fmaf(E.z, wc.w, fmaf(E.w, wd.w, m3))));
        }
        m0 = m0 > 0.f ? m0 : 0.2f * m0;
        m1 = m1 > 0.f ? m1 : 0.2f * m1;
        m2 = m2 > 0.f ? m2 : 0.2f * m2;
        m3 = m3 > 0.f ? m3 : 0.2f * m3;
        float a = m0 * sAv.x + m1 * sAv.y + m2 * sAv.z + m3 * sAv.w;
#pragma unroll
        for (int o = 16; o; o >>= 1) a += __shfl_xor_sync(0xFFFFFFFFu, a, o);

        float ev;
        if (a > amax) {               // warp-uniform branch
            float cc = __expf(amax - a);
            denom *= cc;
            out.x *= cc; out.y *= cc; out.z *= cc; out.w *= cc;
            amax = a;
            ev = 1.0f;
        } else {
            ev = __expf(a - amax);
        }
        denom += ev;
        out.x = fmaf(ev, xl_c.x, out.x); out.y = fmaf(ev, xl_c.y, out.y);
        out.z = fmaf(ev, xl_c.z, out.z); out.w = fmaf(ev, xl_c.w, out.w);

        ec0 = en0; ec1 = en1; ec2 = en2; ec3 = en3; xl_c = xl_n;
    }

    float invd = 1.0f / denom;
    float4 bb = *(const float4*)(bias2 + k0);
    out.x = fmaf(out.x, invd, bb.x); out.y = fmaf(out.y, invd, bb.y);
    out.z = fmaf(out.z, invd, bb.z); out.w = fmaf(out.w, invd, bb.w);

    int g = d_bat[w];
    atomicAdd((float4*)(d_gsum + (size_t)g * OD) + lane, out);
    if (lane == 0) atomicAdd(&d_gcnt[g], 1.0f);
}

// ---------------- FFN head: 4 graphs per block (W1 L2-traffic /4) ---------
__global__ void __launch_bounds__(512)
k_ffn(const float* __restrict__ W1, const float* __restrict__ b1,
      const float* __restrict__ W2, const float* __restrict__ b2,
      float* __restrict__ y) {
    __shared__ float g[4][OD];
    __shared__ float red[512];
    int b0 = blockIdx.x * 4, t = threadIdx.x;
    {
        int gi = t >> 7, k = t & 127;
        float inv = 1.0f / fmaxf(d_gcnt[b0 + gi], 1.0f);
        g[gi][k] = d_gsum[(b0 + gi) * OD + k] * inv;
    }
    __syncthreads();
    float a0 = b1[t], a1 = a0, a2 = a0, a3 = a0;
    for (int k = 0; k < OD; k++) {
        float wv = W1[k * 512 + t];
        a0 = fmaf(g[0][k], wv, a0);
        a1 = fmaf(g[1][k], wv, a1);
        a2 = fmaf(g[2][k], wv, a2);
        a3 = fmaf(g[3][k], wv, a3);
    }
    float w2 = W2[t];
    float part[4] = {gelu_t(a0) * w2, gelu_t(a1) * w2, gelu_t(a2) * w2, gelu_t(a3) * w2};
#pragma unroll
    for (int gi = 0; gi < 4; gi++) {
        red[t] = part[gi];
        __syncthreads();
        for (int o = 256; o; o >>= 1) {
            if (t < o) red[t] += red[t + o];
            __syncthreads();
        }
        if (t == 0) y[b0 + gi] = red[0] + b2[0];
        __syncthreads();
    }
}

// ---------------- launch ----------------
extern "C" void kernel_launch(void* const* d_in, const int* in_sizes, int n_in,
                              void* d_out, int out_size) {
    (void)in_sizes; (void)n_in; (void)out_size;
    const float* x     = (const float*)d_in[0];
    const int*   ei    = (const int*)d_in[1];
    const float* ea    = (const float*)d_in[2];
    const int*   bat   = (const int*)d_in[3];
    const float* Wmsg  = (const float*)d_in[4];
    const float* bmsg  = (const float*)d_in[5];
    const float* We1   = (const float*)d_in[6];
    const float* be1   = (const float*)d_in[7];
    const float* Wself = (const float*)d_in[8];
    const float* bself = (const float*)d_in[9];
    const float* Wl    = (const float*)d_in[10];
    const float* bl    = (const float*)d_in[11];
    const float* Wr    = (const float*)d_in[12];
    const float* br    = (const float*)d_in[13];
    const float* We2   = (const float*)d_in[14];
    const float* att   = (const float*)d_in[15];
    const float* bias2 = (const float*)d_in[16];
    const float* W1    = (const float*)d_in[17];
    const float* b1    = (const float*)d_in[18];
    const float* W2    = (const float*)d_in[19];
    const float* b2    = (const float*)d_in[20];
    float* y = (float*)d_out;

    k_zero<<<512, 256>>>(ei);
    k_convert<<<(NE + 255) / 256, 256>>>(ei, bat);
    k_scanA<<<NSCB, SCB>>>();
    k_scanB<<<1, 256>>>();
    k_scanC<<<NSCB, SCB>>>();
    k_scatcsr<<<(NE + 255) / 256, 256>>>();
    k_gather<<<NN / 8, 256>>>(x, ea);
    k_packw<<<64, 256>>>(Wmsg, Wself, We1, Wl, bl, Wr, br);
    dim3 gg((NN + 127) / 128, 4);
    k_gemm<0><<<gg, 256>>>(x, bmsg, be1, bself);
    k_gemm<1><<<gg, 256>>>(x, nullptr, nullptr, nullptr);
    k_att<<<NN / 8, 256>>>(ea, We2, att, bias2);
    k_ffn<<<NG / 4, 512>>>(W1, b1, W2, b2, y);
}